// round 7
// baseline (speedup 1.0000x reference)
#include <cuda_runtime.h>
#include <cuda_bf16.h>
#include <math.h>

#define MAXN 50000
#define MAXE 800000
#define F1 64      // nfeat
#define F2 128     // nhid
#define F3 64      // nclass
#define EPS 1e-6f

// ---------------- scratch (no allocation allowed) ----------------
__device__ __align__(16) float g_t[MAXN * F3];      // 12.8 MB: relu(h) @ W2
__device__ int g_counts[MAXN];
__device__ int g_rowptr[MAXN + 1];
__device__ int g_cursor[MAXN];
__device__ int g_partials[64];
__device__ int g_sorted_src[MAXE];                   // src ids grouped by dst

// ================= CSR build =================
// 4 edges per thread via int4 loads -> 4 independent atomic chains in flight.
__global__ void hist_kernel(const int* __restrict__ dst, int* __restrict__ counts, int E)
{
    int i0 = (blockIdx.x * blockDim.x + threadIdx.x) * 4;
    if (i0 + 3 < E) {
        int4 d = *(const int4*)(dst + i0);
        atomicAdd(counts + d.x, 1);
        atomicAdd(counts + d.y, 1);
        atomicAdd(counts + d.z, 1);
        atomicAdd(counts + d.w, 1);
    } else {
        for (int i = i0; i < E; i++)
            atomicAdd(counts + __ldg(dst + i), 1);
    }
}

// block = 256 threads, 1024 elements per block
__global__ void scan1_kernel(const int* __restrict__ counts, int* __restrict__ rowptr,
                             int* __restrict__ partials, int N)
{
    __shared__ int s[256];
    int b = blockIdx.x, t = threadIdx.x;
    int base = b * 1024 + t * 4;
    int v[4]; int sum = 0;
    #pragma unroll
    for (int j = 0; j < 4; j++) {
        v[j] = (base + j < N) ? counts[base + j] : 0;
        sum += v[j];
    }
    s[t] = sum;
    __syncthreads();
    #pragma unroll
    for (int off = 1; off < 256; off <<= 1) {
        int x = (t >= off) ? s[t - off] : 0;
        __syncthreads();
        s[t] += x;
        __syncthreads();
    }
    int run = s[t] - sum;
    if (t == 255) partials[b] = s[255];
    #pragma unroll
    for (int j = 0; j < 4; j++) {
        if (base + j < N) rowptr[base + j] = run;
        run += v[j];
    }
}

// merged scan2+scan3: each block locally prefix-sums the (<=64) block partials
__global__ void scan23_kernel(int* __restrict__ rowptr, const int* __restrict__ partials,
                              int* __restrict__ cursor, int nb, int N, int E)
{
    __shared__ int sp[64];
    int t = threadIdx.x;
    int orig = 0;
    if (t < 64) {
        orig = (t < nb) ? partials[t] : 0;
        sp[t] = orig;
    }
    __syncthreads();
    #pragma unroll
    for (int off = 1; off < 64; off <<= 1) {
        int x = (t < 64 && t >= off) ? sp[t - off] : 0;
        __syncthreads();
        if (t < 64) sp[t] += x;
        __syncthreads();
    }
    if (t < 64) sp[t] -= orig;     // exclusive
    __syncthreads();

    int i = blockIdx.x * blockDim.x + t;
    if (i < N) {
        int r = rowptr[i] + sp[i >> 10];
        rowptr[i] = r;
        cursor[i] = r;
    }
    if (i == 0) rowptr[N] = E;
}

// 4 edges per thread: int4 src+dst loads, 4 independent cursor-atomic chains.
__global__ void scatter_kernel(const int* __restrict__ src, const int* __restrict__ dst,
                               int* __restrict__ cursor, int* __restrict__ sorted_src, int E)
{
    int i0 = (blockIdx.x * blockDim.x + threadIdx.x) * 4;
    if (i0 + 3 < E) {
        int4 d = *(const int4*)(dst + i0);
        int4 s = *(const int4*)(src + i0);
        int p0 = atomicAdd(cursor + d.x, 1);
        int p1 = atomicAdd(cursor + d.y, 1);
        int p2 = atomicAdd(cursor + d.z, 1);
        int p3 = atomicAdd(cursor + d.w, 1);
        sorted_src[p0] = s.x;
        sorted_src[p1] = s.y;
        sorted_src[p2] = s.z;
        sorted_src[p3] = s.w;
    } else {
        for (int i = i0; i < E; i++) {
            int pos = atomicAdd(cursor + __ldg(dst + i), 1);
            sorted_src[pos] = __ldg(src + i);
        }
    }
}

// ================= Fused: gather-1 + GEMM1 + relu + GEMM2 =================
// Per 64-node block:
//   A) gather CSR mean of x into As[64][64]; load W1 into Ws[64][128]
//   B) GEMM1: 64x128 register tile (8 rows x 4 cols / thread) + bias
//   C) relu'd tile -> Hs (reusing Ws storage); t = Hs @ W2 in two 64-K chunks
//      (W2 chunks streamed through the As storage); write t.
// h never touches global memory.
__global__ __launch_bounds__(256) void fused12_kernel(const float* __restrict__ x,
                                                      const int* __restrict__ rowptr,
                                                      const int* __restrict__ sorted_src,
                                                      const float* __restrict__ W1,
                                                      const float* __restrict__ b1,
                                                      const float* __restrict__ W2,
                                                      float* __restrict__ t,
                                                      int N)
{
    __shared__ float sbuf[64 * 128 + 64 * 64];   // 48 KB
    float (*Ws)[128] = (float(*)[128])sbuf;                  // W1, then Hs
    float (*As)[64]  = (float(*)[64])(sbuf + 64 * 128);      // mean tile, then W2 chunks

    int tid = threadIdx.x;
    int node0 = blockIdx.x * 64;
    int wid = tid >> 5, lane = tid & 31;
    int hlane = lane & 15, half = lane >> 4;

    // ---- A: load W1 (2048 float4, 8/thread) ----
    #pragma unroll
    for (int i = 0; i < 8; i++) {
        int lin = tid + i * 256;
        ((float4*)Ws)[lin] = ((const float4*)W1)[lin];
    }

    // ---- A: gather means, 2 rows/warp, 16 lanes x float4, MLP-8 ----
    #pragma unroll
    for (int pass = 0; pass < 4; pass++) {
        int row = pass * 16 + wid * 2 + half;
        int node = node0 + row;
        float4 acc = make_float4(0.f, 0.f, 0.f, 0.f);
        int beg = 0, end = 0;
        if (node < N) { beg = __ldg(rowptr + node); end = __ldg(rowptr + node + 1); }
        for (int e = beg; e < end; e += 8) {
            int s[8];
            #pragma unroll
            for (int j = 0; j < 8; j++)
                s[j] = __ldg(sorted_src + min(e + j, end - 1));
            float4 v[8];
            #pragma unroll
            for (int j = 0; j < 8; j++)
                v[j] = ((const float4*)x)[s[j] * 16 + hlane];
            #pragma unroll
            for (int j = 0; j < 8; j++)
                if (e + j < end) {
                    acc.x += v[j].x; acc.y += v[j].y;
                    acc.z += v[j].z; acc.w += v[j].w;
                }
        }
        float inv = 1.0f / ((float)(end - beg) + EPS);
        acc.x *= inv; acc.y *= inv; acc.z *= inv; acc.w *= inv;
        *(float4*)&As[row][hlane * 4] = acc;
    }
    __syncthreads();

    // ---- B: GEMM1 (64x128), 8 rows x 4 cols per thread ----
    int tx = tid & 31, ty = tid >> 5;
    int col0 = tx * 4, row0 = ty * 8;
    float4 acc[8];
    float4 bias = *(const float4*)(b1 + col0);
    #pragma unroll
    for (int r = 0; r < 8; r++) acc[r] = bias;

    #pragma unroll 4
    for (int k = 0; k < 64; k++) {
        float4 w = *(float4*)&Ws[k][col0];
        #pragma unroll
        for (int r = 0; r < 8; r++) {
            float m = As[row0 + r][k];
            acc[r].x = fmaf(m, w.x, acc[r].x);
            acc[r].y = fmaf(m, w.y, acc[r].y);
            acc[r].z = fmaf(m, w.z, acc[r].z);
            acc[r].w = fmaf(m, w.w, acc[r].w);
        }
    }
    __syncthreads();     // S1: everyone done reading Ws/As

    // ---- C: relu -> Hs (Ws storage); load W2 chunk 0 into As ----
    #pragma unroll
    for (int r = 0; r < 8; r++) {
        float4 o;
        o.x = fmaxf(acc[r].x, 0.f);
        o.y = fmaxf(acc[r].y, 0.f);
        o.z = fmaxf(acc[r].z, 0.f);
        o.w = fmaxf(acc[r].w, 0.f);
        *(float4*)&Ws[row0 + r][col0] = o;
    }
    #pragma unroll
    for (int i = 0; i < 4; i++) {
        int lin = tid + i * 256;
        ((float4*)As)[lin] = ((const float4*)W2)[lin];          // chunk 0
    }

    int tx2 = tid & 15, ty2 = tid >> 4;
    int c0 = tx2 * 4, r0 = ty2 * 4;
    float4 acc2[4];
    #pragma unroll
    for (int r = 0; r < 4; r++) acc2[r] = make_float4(0.f, 0.f, 0.f, 0.f);

    #pragma unroll
    for (int c = 0; c < 2; c++) {
        if (c == 1) {
            __syncthreads();     // S3: chunk-0 reads done
            #pragma unroll
            for (int i = 0; i < 4; i++) {
                int lin = tid + i * 256;
                ((float4*)As)[lin] = ((const float4*)W2)[1024 + lin];   // chunk 1
            }
        }
        __syncthreads();         // S2 / S4
        #pragma unroll 4
        for (int k = 0; k < 64; k++) {
            float4 w = *(float4*)&As[k][c0];
            #pragma unroll
            for (int r = 0; r < 4; r++) {
                float m = Ws[r0 + r][c * 64 + k];
                acc2[r].x = fmaf(m, w.x, acc2[r].x);
                acc2[r].y = fmaf(m, w.y, acc2[r].y);
                acc2[r].z = fmaf(m, w.z, acc2[r].z);
                acc2[r].w = fmaf(m, w.w, acc2[r].w);
            }
        }
    }

    #pragma unroll
    for (int r = 0; r < 4; r++) {
        int node = node0 + r0 + r;
        if (node < N)
            *(float4*)(t + node * F3 + c0) = acc2[r];
    }
}

// ================= gather-2 + bias + log_softmax =================
// 2 nodes per warp: 16 lanes x float4 per node, MLP-8 batched loads,
// half-warp shuffle reductions for log_softmax.
__global__ __launch_bounds__(256) void gather2_final_kernel(const float* __restrict__ t,
                                                            const int* __restrict__ rowptr,
                                                            const int* __restrict__ sorted_src,
                                                            const float* __restrict__ b2,
                                                            float* __restrict__ out,
                                                            int N)
{
    int tid = threadIdx.x;
    int wid = tid >> 5, lane = tid & 31;
    int hlane = lane & 15, half = lane >> 4;
    int node = blockIdx.x * 16 + wid * 2 + half;
    if (node >= N) return;

    int beg = __ldg(rowptr + node);
    int end = __ldg(rowptr + node + 1);
    float4 acc = make_float4(0.f, 0.f, 0.f, 0.f);
    for (int e = beg; e < end; e += 8) {
        int s[8];
        #pragma unroll
        for (int j = 0; j < 8; j++)
            s[j] = __ldg(sorted_src + min(e + j, end - 1));
        float4 v[8];
        #pragma unroll
        for (int j = 0; j < 8; j++)
            v[j] = ((const float4*)t)[s[j] * 16 + hlane];
        #pragma unroll
        for (int j = 0; j < 8; j++)
            if (e + j < end) {
                acc.x += v[j].x; acc.y += v[j].y;
                acc.z += v[j].z; acc.w += v[j].w;
            }
    }
    float inv = 1.0f / ((float)(end - beg) + EPS);
    float4 bb = ((const float4*)b2)[hlane];
    float4 v;
    v.x = acc.x * inv + bb.x;
    v.y = acc.y * inv + bb.y;
    v.z = acc.z * inv + bb.z;
    v.w = acc.w * inv + bb.w;

    float m = fmaxf(fmaxf(v.x, v.y), fmaxf(v.z, v.w));
    #pragma unroll
    for (int o = 8; o > 0; o >>= 1)
        m = fmaxf(m, __shfl_xor_sync(0xffffffffu, m, o));
    float s = expf(v.x - m) + expf(v.y - m) + expf(v.z - m) + expf(v.w - m);
    #pragma unroll
    for (int o = 8; o > 0; o >>= 1)
        s += __shfl_xor_sync(0xffffffffu, s, o);
    float l = m + logf(s);

    float4 o4 = make_float4(v.x - l, v.y - l, v.z - l, v.w - l);
    ((float4*)out)[node * 16 + hlane] = o4;
}

extern "C" void kernel_launch(void* const* d_in, const int* in_sizes, int n_in,
                              void* d_out, int out_size)
{
    const float* x   = (const float*)d_in[0];
    const int*   src = (const int*)d_in[1];
    const int*   dst = (const int*)d_in[2];
    const float* W1  = (const float*)d_in[3];
    const float* b1  = (const float*)d_in[4];
    const float* W2  = (const float*)d_in[5];
    const float* b2  = (const float*)d_in[6];
    float* out = (float*)d_out;

    int N = in_sizes[0] / F1;
    int E = in_sizes[1];

    float *t;
    int *counts, *rowptr, *cursor, *partials, *sorted_src;
    cudaGetSymbolAddress((void**)&t, g_t);
    cudaGetSymbolAddress((void**)&counts, g_counts);
    cudaGetSymbolAddress((void**)&rowptr, g_rowptr);
    cudaGetSymbolAddress((void**)&cursor, g_cursor);
    cudaGetSymbolAddress((void**)&partials, g_partials);
    cudaGetSymbolAddress((void**)&sorted_src, g_sorted_src);

    // ---- CSR build ----
    cudaMemsetAsync(counts, 0, (size_t)N * sizeof(int), 0);
    int et = (E + 3) / 4;     // threads for 4-edge-per-thread kernels
    hist_kernel<<<(et + 255) / 256, 256, 0, 0>>>(dst, counts, E);
    int nb = (N + 1023) / 1024;
    scan1_kernel<<<nb, 256, 0, 0>>>(counts, rowptr, partials, N);
    scan23_kernel<<<(N + 255) / 256, 256, 0, 0>>>(rowptr, partials, cursor, nb, N, E);
    scatter_kernel<<<(et + 255) / 256, 256, 0, 0>>>(src, dst, cursor, sorted_src, E);

    // ---- layers 1+2a fused: gather(mean) -> W1+b1+relu -> @W2 -> t ----
    fused12_kernel<<<(N + 63) / 64, 256, 0, 0>>>(x, rowptr, sorted_src, W1, b1, W2, t, N);

    // ---- layer 2b: gather(mean) + b2 + log_softmax ----
    gather2_final_kernel<<<(N + 15) / 16, 256, 0, 0>>>(t, rowptr, sorted_src, b2, out, N);
}

// round 8
// speedup vs baseline: 1.0250x; 1.0250x over previous
#include <cuda_runtime.h>
#include <cuda_bf16.h>
#include <math.h>

#define MAXN 50000
#define MAXE 800000
#define F1 64      // nfeat
#define F2 128     // nhid
#define F3 64      // nclass
#define EPS 1e-6f

// ---------------- scratch (no allocation allowed) ----------------
__device__ __align__(16) float g_t[MAXN * F3];      // 12.8 MB: relu(h) @ W2
__device__ int g_counts[MAXN];
__device__ int g_rowptr[MAXN + 1];
__device__ int g_partials[64];
__device__ __align__(16) int g_rank[MAXE];           // edge rank within its dst bucket
__device__ int g_sorted_src[MAXE];                   // src ids grouped by dst

// ================= CSR build =================
// hist: count edges per dst AND capture each edge's rank within its bucket
// (the atomicAdd return value we previously discarded).
__global__ void hist_kernel(const int* __restrict__ dst, int* __restrict__ counts,
                            int* __restrict__ rank, int E)
{
    int i = blockIdx.x * blockDim.x + threadIdx.x;
    if (i < E)
        rank[i] = atomicAdd(counts + __ldg(dst + i), 1);
}

// block = 256 threads, 1024 elements per block
__global__ void scan1_kernel(const int* __restrict__ counts, int* __restrict__ rowptr,
                             int* __restrict__ partials, int N)
{
    __shared__ int s[256];
    int b = blockIdx.x, t = threadIdx.x;
    int base = b * 1024 + t * 4;
    int v[4]; int sum = 0;
    #pragma unroll
    for (int j = 0; j < 4; j++) {
        v[j] = (base + j < N) ? counts[base + j] : 0;
        sum += v[j];
    }
    s[t] = sum;
    __syncthreads();
    #pragma unroll
    for (int off = 1; off < 256; off <<= 1) {
        int x = (t >= off) ? s[t - off] : 0;
        __syncthreads();
        s[t] += x;
        __syncthreads();
    }
    int run = s[t] - sum;
    if (t == 255) partials[b] = s[255];
    #pragma unroll
    for (int j = 0; j < 4; j++) {
        if (base + j < N) rowptr[base + j] = run;
        run += v[j];
    }
}

// merged scan2+scan3: each block locally prefix-sums the (<=64) block partials
__global__ void scan23_kernel(int* __restrict__ rowptr, const int* __restrict__ partials,
                              int nb, int N, int E)
{
    __shared__ int sp[64];
    int t = threadIdx.x;
    int orig = 0;
    if (t < 64) {
        orig = (t < nb) ? partials[t] : 0;
        sp[t] = orig;
    }
    __syncthreads();
    #pragma unroll
    for (int off = 1; off < 64; off <<= 1) {
        int x = (t < 64 && t >= off) ? sp[t - off] : 0;
        __syncthreads();
        if (t < 64) sp[t] += x;
        __syncthreads();
    }
    if (t < 64) sp[t] -= orig;     // exclusive
    __syncthreads();

    int i = blockIdx.x * blockDim.x + t;
    if (i < N)
        rowptr[i] += sp[i >> 10];
    if (i == 0) rowptr[N] = E;
}

// ATOMIC-FREE scatter: position = rowptr[dst] + rank. 4 edges/thread, int4 loads.
__global__ void scatter_kernel(const int* __restrict__ src, const int* __restrict__ dst,
                               const int* __restrict__ rowptr, const int* __restrict__ rank,
                               int* __restrict__ sorted_src, int E)
{
    int i0 = (blockIdx.x * blockDim.x + threadIdx.x) * 4;
    if (i0 + 3 < E) {
        int4 d = *(const int4*)(dst + i0);
        int4 s = *(const int4*)(src + i0);
        int4 r = *(const int4*)(rank + i0);
        sorted_src[__ldg(rowptr + d.x) + r.x] = s.x;
        sorted_src[__ldg(rowptr + d.y) + r.y] = s.y;
        sorted_src[__ldg(rowptr + d.z) + r.z] = s.z;
        sorted_src[__ldg(rowptr + d.w) + r.w] = s.w;
    } else {
        for (int i = i0; i < E; i++)
            sorted_src[__ldg(rowptr + __ldg(dst + i)) + __ldg(rank + i)] = __ldg(src + i);
    }
}

// ================= Fused: gather-1 + GEMM1 + relu + GEMM2 =================
// Per 64-node block:
//   A) gather CSR mean of x into As[64][64]; load W1 into Ws[64][128]
//   B) GEMM1: 64x128 register tile (8 rows x 4 cols / thread) + bias
//   C) relu'd tile -> Hs (reusing Ws storage); t = Hs @ W2 in two 64-K chunks
//      (W2 chunks streamed through the As storage); write t.
// h never touches global memory.
__global__ __launch_bounds__(256) void fused12_kernel(const float* __restrict__ x,
                                                      const int* __restrict__ rowptr,
                                                      const int* __restrict__ sorted_src,
                                                      const float* __restrict__ W1,
                                                      const float* __restrict__ b1,
                                                      const float* __restrict__ W2,
                                                      float* __restrict__ t,
                                                      int N)
{
    __shared__ float sbuf[64 * 128 + 64 * 64];   // 48 KB
    float (*Ws)[128] = (float(*)[128])sbuf;                  // W1, then Hs
    float (*As)[64]  = (float(*)[64])(sbuf + 64 * 128);      // mean tile, then W2 chunks

    int tid = threadIdx.x;
    int node0 = blockIdx.x * 64;
    int wid = tid >> 5, lane = tid & 31;
    int hlane = lane & 15, half = lane >> 4;

    // ---- A: load W1 (2048 float4, 8/thread) ----
    #pragma unroll
    for (int i = 0; i < 8; i++) {
        int lin = tid + i * 256;
        ((float4*)Ws)[lin] = ((const float4*)W1)[lin];
    }

    // ---- A: gather means, 2 rows/warp, 16 lanes x float4, MLP-8 ----
    #pragma unroll
    for (int pass = 0; pass < 4; pass++) {
        int row = pass * 16 + wid * 2 + half;
        int node = node0 + row;
        float4 acc = make_float4(0.f, 0.f, 0.f, 0.f);
        int beg = 0, end = 0;
        if (node < N) { beg = __ldg(rowptr + node); end = __ldg(rowptr + node + 1); }
        for (int e = beg; e < end; e += 8) {
            int s[8];
            #pragma unroll
            for (int j = 0; j < 8; j++)
                s[j] = __ldg(sorted_src + min(e + j, end - 1));
            float4 v[8];
            #pragma unroll
            for (int j = 0; j < 8; j++)
                v[j] = ((const float4*)x)[s[j] * 16 + hlane];
            #pragma unroll
            for (int j = 0; j < 8; j++)
                if (e + j < end) {
                    acc.x += v[j].x; acc.y += v[j].y;
                    acc.z += v[j].z; acc.w += v[j].w;
                }
        }
        float inv = 1.0f / ((float)(end - beg) + EPS);
        acc.x *= inv; acc.y *= inv; acc.z *= inv; acc.w *= inv;
        *(float4*)&As[row][hlane * 4] = acc;
    }
    __syncthreads();

    // ---- B: GEMM1 (64x128), 8 rows x 4 cols per thread ----
    int tx = tid & 31, ty = tid >> 5;
    int col0 = tx * 4, row0 = ty * 8;
    float4 acc[8];
    float4 bias = *(const float4*)(b1 + col0);
    #pragma unroll
    for (int r = 0; r < 8; r++) acc[r] = bias;

    #pragma unroll 4
    for (int k = 0; k < 64; k++) {
        float4 w = *(float4*)&Ws[k][col0];
        #pragma unroll
        for (int r = 0; r < 8; r++) {
            float m = As[row0 + r][k];
            acc[r].x = fmaf(m, w.x, acc[r].x);
            acc[r].y = fmaf(m, w.y, acc[r].y);
            acc[r].z = fmaf(m, w.z, acc[r].z);
            acc[r].w = fmaf(m, w.w, acc[r].w);
        }
    }
    __syncthreads();     // S1: everyone done reading Ws/As

    // ---- C: relu -> Hs (Ws storage); load W2 chunk 0 into As ----
    #pragma unroll
    for (int r = 0; r < 8; r++) {
        float4 o;
        o.x = fmaxf(acc[r].x, 0.f);
        o.y = fmaxf(acc[r].y, 0.f);
        o.z = fmaxf(acc[r].z, 0.f);
        o.w = fmaxf(acc[r].w, 0.f);
        *(float4*)&Ws[row0 + r][col0] = o;
    }
    #pragma unroll
    for (int i = 0; i < 4; i++) {
        int lin = tid + i * 256;
        ((float4*)As)[lin] = ((const float4*)W2)[lin];          // chunk 0
    }

    int tx2 = tid & 15, ty2 = tid >> 4;
    int c0 = tx2 * 4, r0 = ty2 * 4;
    float4 acc2[4];
    #pragma unroll
    for (int r = 0; r < 4; r++) acc2[r] = make_float4(0.f, 0.f, 0.f, 0.f);

    #pragma unroll
    for (int c = 0; c < 2; c++) {
        if (c == 1) {
            __syncthreads();     // S3: chunk-0 reads done
            #pragma unroll
            for (int i = 0; i < 4; i++) {
                int lin = tid + i * 256;
                ((float4*)As)[lin] = ((const float4*)W2)[1024 + lin];   // chunk 1
            }
        }
        __syncthreads();         // S2 / S4
        #pragma unroll 4
        for (int k = 0; k < 64; k++) {
            float4 w = *(float4*)&As[k][c0];
            #pragma unroll
            for (int r = 0; r < 4; r++) {
                float m = Ws[r0 + r][c * 64 + k];
                acc2[r].x = fmaf(m, w.x, acc2[r].x);
                acc2[r].y = fmaf(m, w.y, acc2[r].y);
                acc2[r].z = fmaf(m, w.z, acc2[r].z);
                acc2[r].w = fmaf(m, w.w, acc2[r].w);
            }
        }
    }

    #pragma unroll
    for (int r = 0; r < 4; r++) {
        int node = node0 + r0 + r;
        if (node < N)
            *(float4*)(t + node * F3 + c0) = acc2[r];
    }
}

// ================= gather-2 + bias + log_softmax =================
// 2 nodes per warp: 16 lanes x float4 per node, MLP-8 batched loads,
// half-warp shuffle reductions for log_softmax.
__global__ __launch_bounds__(256) void gather2_final_kernel(const float* __restrict__ t,
                                                            const int* __restrict__ rowptr,
                                                            const int* __restrict__ sorted_src,
                                                            const float* __restrict__ b2,
                                                            float* __restrict__ out,
                                                            int N)
{
    int tid = threadIdx.x;
    int wid = tid >> 5, lane = tid & 31;
    int hlane = lane & 15, half = lane >> 4;
    int node = blockIdx.x * 16 + wid * 2 + half;
    if (node >= N) return;

    int beg = __ldg(rowptr + node);
    int end = __ldg(rowptr + node + 1);
    float4 acc = make_float4(0.f, 0.f, 0.f, 0.f);
    for (int e = beg; e < end; e += 8) {
        int s[8];
        #pragma unroll
        for (int j = 0; j < 8; j++)
            s[j] = __ldg(sorted_src + min(e + j, end - 1));
        float4 v[8];
        #pragma unroll
        for (int j = 0; j < 8; j++)
            v[j] = ((const float4*)t)[s[j] * 16 + hlane];
        #pragma unroll
        for (int j = 0; j < 8; j++)
            if (e + j < end) {
                acc.x += v[j].x; acc.y += v[j].y;
                acc.z += v[j].z; acc.w += v[j].w;
            }
    }
    float inv = 1.0f / ((float)(end - beg) + EPS);
    float4 bb = ((const float4*)b2)[hlane];
    float4 v;
    v.x = acc.x * inv + bb.x;
    v.y = acc.y * inv + bb.y;
    v.z = acc.z * inv + bb.z;
    v.w = acc.w * inv + bb.w;

    float m = fmaxf(fmaxf(v.x, v.y), fmaxf(v.z, v.w));
    #pragma unroll
    for (int o = 8; o > 0; o >>= 1)
        m = fmaxf(m, __shfl_xor_sync(0xffffffffu, m, o));
    float s = expf(v.x - m) + expf(v.y - m) + expf(v.z - m) + expf(v.w - m);
    #pragma unroll
    for (int o = 8; o > 0; o >>= 1)
        s += __shfl_xor_sync(0xffffffffu, s, o);
    float l = m + logf(s);

    float4 o4 = make_float4(v.x - l, v.y - l, v.z - l, v.w - l);
    ((float4*)out)[node * 16 + hlane] = o4;
}

extern "C" void kernel_launch(void* const* d_in, const int* in_sizes, int n_in,
                              void* d_out, int out_size)
{
    const float* x   = (const float*)d_in[0];
    const int*   src = (const int*)d_in[1];
    const int*   dst = (const int*)d_in[2];
    const float* W1  = (const float*)d_in[3];
    const float* b1  = (const float*)d_in[4];
    const float* W2  = (const float*)d_in[5];
    const float* b2  = (const float*)d_in[6];
    float* out = (float*)d_out;

    int N = in_sizes[0] / F1;
    int E = in_sizes[1];

    float *t;
    int *counts, *rowptr, *partials, *rank, *sorted_src;
    cudaGetSymbolAddress((void**)&t, g_t);
    cudaGetSymbolAddress((void**)&counts, g_counts);
    cudaGetSymbolAddress((void**)&rowptr, g_rowptr);
    cudaGetSymbolAddress((void**)&partials, g_partials);
    cudaGetSymbolAddress((void**)&rank, g_rank);
    cudaGetSymbolAddress((void**)&sorted_src, g_sorted_src);

    // ---- CSR build ----
    cudaMemsetAsync(counts, 0, (size_t)N * sizeof(int), 0);
    hist_kernel<<<(E + 255) / 256, 256, 0, 0>>>(dst, counts, rank, E);
    int nb = (N + 1023) / 1024;
    scan1_kernel<<<nb, 256, 0, 0>>>(counts, rowptr, partials, N);
    scan23_kernel<<<(N + 255) / 256, 256, 0, 0>>>(rowptr, partials, nb, N, E);
    int et = (E + 3) / 4;
    scatter_kernel<<<(et + 255) / 256, 256, 0, 0>>>(src, dst, rowptr, rank, sorted_src, E);

    // ---- layers 1+2a fused: gather(mean) -> W1+b1+relu -> @W2 -> t ----
    fused12_kernel<<<(N + 63) / 64, 256, 0, 0>>>(x, rowptr, sorted_src, W1, b1, W2, t, N);

    // ---- layer 2b: gather(mean) + b2 + log_softmax ----
    gather2_final_kernel<<<(N + 15) / 16, 256, 0, 0>>>(t, rowptr, sorted_src, b2, out, N);
}